// round 16
// baseline (speedup 1.0000x reference)
#include <cuda_runtime.h>
#include <math.h>
#include <stdint.h>

#define NN 50000
#define EE 800000
#define NPB 16    // nodes per k_gat block (NN % NPB == 0)
#define CHK 128   // edges per staged chunk

typedef unsigned long long ull;

// ---------------- scratch (device globals) ----------------------------------
__device__ int g_cnt[NN];
__device__ int g_rowptr[NN];
__device__ int g_rowfill[NN];
__device__ int g_aux[128];
__device__ int g_src_sorted[EE];
__device__ int g_eid_sorted[EE];
__device__ __align__(16) ull   g_e2[(size_t)EE * 16];   // edge feats, dup-packed f32x2, sorted order
__device__ __align__(16) float g_L[(size_t)NN * 512];
__device__ __align__(16) float g_R[(size_t)NN * 512];
__device__ __align__(16) float g_NUM[(size_t)NN * 512];
__device__ float g_DEN[(size_t)NN * 16];

// ---------------- helpers ----------------------------------------------------
__device__ __forceinline__ ull pack2(float a, float b) {
    ull r; asm("mov.b64 %0,{%1,%2};" : "=l"(r) : "f"(a), "f"(b)); return r;
}
__device__ __forceinline__ void unpack2(float& a, float& b, ull v) {
    asm("mov.b64 {%0,%1},%2;" : "=f"(a), "=f"(b) : "l"(v));
}
__device__ __forceinline__ ull fma2(ull a, ull b, ull c) {
    ull d; asm("fma.rn.f32x2 %0,%1,%2,%3;" : "=l"(d) : "l"(a), "l"(b), "l"(c)); return d;
}
__device__ __forceinline__ ull add2(ull a, ull b) {
    ull d; asm("add.rn.f32x2 %0,%1,%2;" : "=l"(d) : "l"(a), "l"(b)); return d;
}
__device__ __forceinline__ ull mul2(ull a, ull b) {
    ull d; asm("mul.rn.f32x2 %0,%1,%2;" : "=l"(d) : "l"(a), "l"(b)); return d;
}
// L2 eviction policies (createpolicy + cache_hint)
__device__ __forceinline__ ull policy_evict_last() {
    ull p; asm("createpolicy.fractional.L2::evict_last.b64 %0, 1.0;" : "=l"(p));
    return p;
}
__device__ __forceinline__ ull policy_evict_first() {
    ull p; asm("createpolicy.fractional.L2::evict_first.b64 %0, 1.0;" : "=l"(p));
    return p;
}
// sticky-L2 gather load (8B: one f32x2 channel pair)
__device__ __forceinline__ ull ldg_el8(const float* p, ull pol) {
    ull v;
    asm("ld.global.nc.L2::cache_hint.b64 %0,[%1],%2;" : "=l"(v) : "l"(p), "l"(pol));
    return v;
}
// streaming 8B store
__device__ __forceinline__ void stg_ef8(float* p, ull a, ull pol) {
    asm volatile("st.global.L2::cache_hint.b64 [%0],%1,%2;"
                 :: "l"(p), "l"(a), "l"(pol) : "memory");
}
__device__ __forceinline__ void cp16(void* smem, const void* g) {
    uint32_t a = (uint32_t)__cvta_generic_to_shared(smem);
    asm volatile("cp.async.ca.shared.global [%0], [%1], 16;" :: "r"(a), "l"(g));
}
__device__ __forceinline__ void cp4(void* smem, const void* g) {
    uint32_t a = (uint32_t)__cvta_generic_to_shared(smem);
    asm volatile("cp.async.ca.shared.global [%0], [%1], 4;" :: "r"(a), "l"(g));
}

// ---------------- counting sort by dst ---------------------------------------
__global__ void k_init() {
    int i = blockIdx.x * 256 + threadIdx.x;
    if (i < NN) g_cnt[i] = 0;
}
__global__ void k_hist(const int* __restrict__ ei) {
    int e = blockIdx.x * 256 + threadIdx.x;
    atomicAdd(&g_cnt[ei[EE + e]], 1);
}
__global__ void k_scan_a() {
    __shared__ int s[512];
    int t = threadIdx.x;
    int i = blockIdx.x * 512 + t;
    int v = (i < NN) ? g_cnt[i] : 0;
    s[t] = v;
    __syncthreads();
#pragma unroll
    for (int off = 1; off < 512; off <<= 1) {
        int u = (t >= off) ? s[t - off] : 0;
        __syncthreads();
        s[t] += u;
        __syncthreads();
    }
    if (i < NN) g_rowptr[i] = s[t] - v;
    if (t == 511) g_aux[blockIdx.x] = s[511];
}
__global__ void k_scan_c() {
    __shared__ int soff;
    int t = threadIdx.x;
    if (t < 32) {
        int sum = 0;
        for (int i = t; i < (int)blockIdx.x; i += 32) sum += g_aux[i];
#pragma unroll
        for (int off = 16; off; off >>= 1)
            sum += __shfl_xor_sync(0xffffffffu, sum, off);
        if (t == 0) soff = sum;
    }
    __syncthreads();
    int i = blockIdx.x * 512 + t;
    if (i < NN) {
        int v = g_rowptr[i] + soff;
        g_rowptr[i] = v;
        g_rowfill[i] = v;
    }
}
__global__ void k_scatter(const int* __restrict__ ei) {
    int e = blockIdx.x * 256 + threadIdx.x;
    int d = ei[EE + e];
    int pos = atomicAdd(&g_rowfill[d], 1);
    g_src_sorted[pos] = ei[e];
    g_eid_sorted[pos] = e;
}

// ---------------- edge MLP (into sorted slots, dup-packed) -------------------
__global__ void k_edge_mlp(const float* __restrict__ ea,
                           const float* __restrict__ Wm1, const float* __restrict__ bm1,
                           const float* __restrict__ Wm2, const float* __restrict__ bm2) {
    __shared__ float sW1[256], sW2[256], sb1[16], sb2[16];
    int t = threadIdx.x;
    sW1[t] = Wm1[t];
    sW2[t] = Wm2[t];
    if (t < 16) { sb1[t] = bm1[t]; sb2[t] = bm2[t]; }
    __syncthreads();
    int i = blockIdx.x * 256 + t;
    int eid = g_eid_sorted[i];

    float4 va[4];
    const float4* p = (const float4*)(ea + (size_t)eid * 16);
    va[0] = p[0]; va[1] = p[1]; va[2] = p[2]; va[3] = p[3];
    const float* a = (const float*)va;

    float h[16];
#pragma unroll
    for (int j = 0; j < 16; j++) {
        float s = sb1[j];
#pragma unroll
        for (int k = 0; k < 16; k++) s = fmaf(a[k], sW1[k * 16 + j], s);
        h[j] = 0.5f * s * (1.0f + erff(s * 0.70710678118654752f));
    }
    ull* q = g_e2 + (size_t)i * 16;
#pragma unroll
    for (int j = 0; j < 16; j++) {
        float s = sb2[j];
#pragma unroll
        for (int k = 0; k < 16; k++) s = fmaf(h[k], sW2[k * 16 + j], s);
        q[j] = pack2(s, s);
    }
}

// ---------------- node projections (z-split over gate chunks, f32x2) --------
template <int IN>
__global__ void k_proj(const float* __restrict__ X,
                       const float* __restrict__ W0, const float* __restrict__ B0,
                       const float* __restrict__ W1, const float* __restrict__ B1,
                       int poff) {
    const float* __restrict__ W = blockIdx.y ? W1 : W0;
    const float* __restrict__ B = blockIdx.y ? B1 : B0;
    float* __restrict__ OUT = blockIdx.y ? g_R : g_L;
    int cc = blockIdx.z;

    __shared__ __align__(16) float xs[64 * (IN + 1)];
    __shared__ __align__(16) float ws[IN * 64];
    int t = threadIdx.x;
    int n0 = blockIdx.x * 64;
    for (int idx = t; idx < 64 * IN; idx += 256) {
        int nl = idx / IN, i = idx % IN;
        int n = n0 + nl;
        xs[nl * (IN + 1) + i] = (n < NN) ? X[(size_t)n * IN + i] : 0.f;
    }
    for (int idx = t; idx < IN * 64; idx += 256)
        ws[idx] = W[cc * IN * 64 + idx];
    __syncthreads();

    int nq = t & 15, cq = t >> 4;
    int c0 = cq * 4;
    ull acc[4][2];
#pragma unroll
    for (int r = 0; r < 4; r++) { acc[r][0] = 0; acc[r][1] = 0; }
#pragma unroll 8
    for (int i = 0; i < IN; i++) {
        const ull* wp = (const ull*)&ws[i * 64 + c0];
        ull b01 = wp[0], b23 = wp[1];
#pragma unroll
        for (int r = 0; r < 4; r++) {
            float av = xs[(nq * 4 + r) * (IN + 1) + i];
            ull av2 = pack2(av, av);
            acc[r][0] = fma2(av2, b01, acc[r][0]);
            acc[r][1] = fma2(av2, b23, acc[r][1]);
        }
    }
    float4 bb = *(const float4*)&B[cc * 64 + c0];
    ull bb01 = pack2(bb.x, bb.y), bb23 = pack2(bb.z, bb.w);
#pragma unroll
    for (int r = 0; r < 4; r++) {
        int n = n0 + nq * 4 + r;
        if (n < NN) {
            ulonglong2 ov;
            ov.x = add2(acc[r][0], bb01);
            ov.y = add2(acc[r][1], bb23);
            *(ulonglong2*)&OUT[(size_t)n * 512 + poff + cc * 64 + c0] = ov;
        }
    }
}

// ---------------- fused GAT pass (pass-split for occupancy) ------------------
// gridDim.y = 2 selects the pass p (0: x-GAT, 1: h-GAT). Block = 128 thr =
// 4 warps; warp w owns gate g=w of that pass (64 channels); lane owns 2
// channels -> 16 ull weight regs (~64 total regs) -> 6 blocks/SM = 24 warps.
// Same chunked double-buffered cp.async staging (both passes read the same
// chunks; second reader hits L2). Softmax segment = 32 ch = 16 lanes.
__global__ __launch_bounds__(128, 6)
void k_gat(const float* __restrict__ Wex, const float* __restrict__ attx,
           const float* __restrict__ Weh, const float* __restrict__ atth) {
    __shared__ __align__(16) ull se[2][CHK * 16];
    __shared__ int ssrc[2][CHK];
    __shared__ int srow_s[NPB + 1];
    int t = threadIdx.x, w = t >> 5, lane = t & 31;
    int n0 = blockIdx.x * NPB;
    if (t <= NPB) srow_s[t] = (n0 + t >= NN) ? EE : g_rowptr[n0 + t];

    const ull POL_L = policy_evict_last();
    const ull POL_F = policy_evict_first();

    int p = blockIdx.y;
    int g = w;
    int c = lane * 2;                      // channel within gate
    int ch0 = p * 256 + g * 64 + c;        // concat channel offset
    const float* __restrict__ We = p ? Weh : Wex;
    const float* __restrict__ att = p ? atth : attx;

    ull sw[16];
#pragma unroll
    for (int k = 0; k < 16; k++) {
        float2 wv = *(const float2*)&We[(g * 16 + k) * 64 + c];
        sw[k] = pack2(wv.x, wv.y);
    }
    float2 a2 = *(const float2*)&att[g * 64 + c];
    int qi = p * 8 + g * 2 + (lane >> 4);
    const ull C02 = pack2(0.2f, 0.2f);
    __syncthreads();

    int gstart = srow_s[0];
    int T = srow_s[NPB] - gstart;
    int nchunks = (T + CHK - 1) / CHK;

    int nl = 0;
    ull num = 0;
    float den = 0.f;
    ull xr, xrn;
    xr  = *(const ull*)(g_R + (size_t)n0 * 512 + ch0);
    xrn = *(const ull*)(g_R + (size_t)(n0 + 1) * 512 + ch0);

    // stage chunk 0 (sequential burst)
    if (nchunks > 0) {
        int cnt0 = min(CHK, T);
        const char* gf = (const char*)(g_e2 + (size_t)gstart * 16);
        for (int i = t; i < cnt0 * 8; i += 128)
            cp16((char*)se[0] + i * 16, gf + i * 16);
        if (t < cnt0) cp4(&ssrc[0][t], &g_src_sorted[gstart + t]);
        asm volatile("cp.async.commit_group;");
    }

    for (int ci = 0; ci < nchunks; ci++) {
        int base = ci * CHK;
        int cnt = min(CHK, T - base);
        int buf = ci & 1;
        if (ci + 1 < nchunks) {
            int nb = (ci + 1) & 1;
            int base2 = base + CHK;
            int cnt2 = min(CHK, T - base2);
            const char* gf = (const char*)(g_e2 + (size_t)(gstart + base2) * 16);
            for (int i = t; i < cnt2 * 8; i += 128)
                cp16((char*)se[nb] + i * 16, gf + i * 16);
            if (t < cnt2) cp4(&ssrc[nb][t], &g_src_sorted[gstart + base2 + t]);
            asm volatile("cp.async.commit_group;");
            asm volatile("cp.async.wait_group 1;" ::: "memory");
        } else {
            asm volatile("cp.async.wait_group 0;" ::: "memory");
        }
        __syncthreads();

        int cbeg = gstart + base, cend = cbeg + cnt;
        // xl prefetch pipeline, depth 2 (sticky L2, 8B per lane)
        ull xlA, xlB;
        {
            int s0 = ssrc[buf][0];
            xlA = ldg_el8(g_L + (size_t)s0 * 512 + ch0, POL_L);
            int s1i = ssrc[buf][cnt > 1 ? 1 : 0];
            xlB = ldg_el8(g_L + (size_t)s1i * 512 + ch0, POL_L);
        }
        while (nl < NPB) {
            int nbeg = srow_s[nl] > cbeg ? srow_s[nl] : cbeg;
            int nend = srow_s[nl + 1] < cend ? srow_s[nl + 1] : cend;
#pragma unroll 4
            for (int ge = nbeg; ge < nend; ge++) {
                int j = ge - cbeg;
                ull xl = xlA;
                xlA = xlB;
                {
                    int jn = (j + 2 < cnt) ? j + 2 : cnt - 1;
                    int sn = ssrc[buf][jn];
                    xlB = ldg_el8(g_L + (size_t)sn * 512 + ch0, POL_L);
                }
                const ulonglong2* ep = (const ulonglong2*)&se[buf][j * 16];
                ull a0 = 0, b0 = 0;
#pragma unroll
                for (int k2 = 0; k2 < 8; k2++) {
                    ulonglong2 ek = ep[k2];
                    a0 = fma2(ek.x, sw[k2 * 2], a0);
                    b0 = fma2(ek.y, sw[k2 * 2 + 1], b0);
                }
                ull acc = add2(add2(a0, b0), add2(xl, xr));
                ull sx = mul2(acc, C02);
                float m0, m1, q0, q1;
                unpack2(m0, m1, acc);
                unpack2(q0, q1, sx);
                float l0 = fmaxf(m0, q0), l1 = fmaxf(m1, q1);
                float sc = fmaf(l0, a2.x, l1 * a2.y);
                sc += __shfl_xor_sync(0xffffffffu, sc, 1);
                sc += __shfl_xor_sync(0xffffffffu, sc, 2);
                sc += __shfl_xor_sync(0xffffffffu, sc, 4);
                sc += __shfl_xor_sync(0xffffffffu, sc, 8);
                float ex = __expf(sc);
                den += ex;
                num = fma2(pack2(ex, ex), xl, num);
            }
            if (srow_s[nl + 1] <= cend) {
                stg_ef8(g_NUM + (size_t)(n0 + nl) * 512 + ch0, num, POL_F);
                if ((lane & 15) == 0) g_DEN[(size_t)(n0 + nl) * 16 + qi] = den;
                nl++;
                num = 0;
                den = 0.f;
                xr = xrn;
                if (nl + 1 < NPB)
                    xrn = *(const ull*)(g_R + (size_t)(n0 + nl + 1) * 512 + ch0);
            } else {
                break;
            }
        }
        __syncthreads();
    }
    // flush any remaining (all-empty trailing nodes)
    while (nl < NPB) {
        stg_ef8(g_NUM + (size_t)(n0 + nl) * 512 + ch0, num, POL_F);
        if ((lane & 15) == 0) g_DEN[(size_t)(n0 + nl) * 16 + qi] = den;
        nl++;
        num = 0;
        den = 0.f;
    }
}

// ---------------- final: normalize, LSTM gates, LayerNorm -------------------
__global__ void k_final(const float* __restrict__ c_prev,
                        const float* __restrict__ biasx, const float* __restrict__ biash,
                        const float* __restrict__ gamma, const float* __restrict__ beta,
                        float* __restrict__ out) {
    int w = threadIdx.x >> 5, lane = threadIdx.x & 31;
    int n = blockIdx.x * 8 + w;
    float res[2], cs[2];
    float sum = 0.f, sq = 0.f;
#pragma unroll
    for (int half = 0; half < 2; half++) {
        int ch = lane + half * 32;
        int hh = ch >> 5;
        float a[4];
#pragma unroll
        for (int g = 0; g < 4; g++) {
            float nx = g_NUM[(size_t)n * 512 + g * 64 + ch];
            float nh = g_NUM[(size_t)n * 512 + 256 + g * 64 + ch];
            float dx = g_DEN[(size_t)n * 16 + g * 2 + hh] + 1e-16f;
            float dh = g_DEN[(size_t)n * 16 + 8 + g * 2 + hh] + 1e-16f;
            a[g] = nx / dx + nh / dh + biasx[g * 64 + ch] + biash[g * 64 + ch];
        }
        float it = 1.f / (1.f + __expf(-a[0]));
        float ft = 1.f / (1.f + __expf(-a[1]));
        float ot = 1.f / (1.f + __expf(-a[2]));
        float gt = tanhf(a[3]);
        float cp = c_prev[(size_t)n * 64 + ch];
        float c = ft * cp + it * gt;
        float hp = ot * tanhf(c);
        cs[half] = c;
        res[half] = hp;
        sum += hp;
        sq = fmaf(hp, hp, sq);
    }
#pragma unroll
    for (int off = 16; off; off >>= 1) {
        sum += __shfl_xor_sync(0xffffffffu, sum, off);
        sq += __shfl_xor_sync(0xffffffffu, sq, off);
    }
    float mu = sum * (1.f / 64.f);
    float var = sq * (1.f / 64.f) - mu * mu;
    float inv = rsqrtf(var + 1e-5f);
#pragma unroll
    for (int half = 0; half < 2; half++) {
        int ch = lane + half * 32;
        float hn = (res[half] - mu) * inv * gamma[ch] + beta[ch];
        out[(size_t)n * 64 + ch] = hn;
        out[(size_t)NN * 64 + (size_t)n * 64 + ch] = cs[half];
    }
}

// ---------------- launch ------------------------------------------------------
extern "C" void kernel_launch(void* const* d_in, const int* in_sizes, int n_in,
                              void* d_out, int out_size) {
    const float* x_t    = (const float*)d_in[0];
    const float* h_prev = (const float*)d_in[1];
    const float* c_prev = (const float*)d_in[2];
    const int*   ei     = (const int*)d_in[3];
    const float* ea     = (const float*)d_in[4];
    const float* Wm1    = (const float*)d_in[5];
    const float* bm1    = (const float*)d_in[6];
    const float* Wm2    = (const float*)d_in[7];
    const float* bm2    = (const float*)d_in[8];
    const float* Wlx    = (const float*)d_in[9];
    const float* blx    = (const float*)d_in[10];
    const float* Wrx    = (const float*)d_in[11];
    const float* brx    = (const float*)d_in[12];
    const float* Wex    = (const float*)d_in[13];
    const float* attx   = (const float*)d_in[14];
    const float* biasx  = (const float*)d_in[15];
    const float* Wlh    = (const float*)d_in[16];
    const float* blh    = (const float*)d_in[17];
    const float* Wrh    = (const float*)d_in[18];
    const float* brh    = (const float*)d_in[19];
    const float* Weh    = (const float*)d_in[20];
    const float* atth   = (const float*)d_in[21];
    const float* biash  = (const float*)d_in[22];
    const float* gamma  = (const float*)d_in[23];
    const float* beta   = (const float*)d_in[24];

    // one-time stream/event setup (no device memory involved)
    static cudaStream_t s1 = nullptr, s2 = nullptr;
    static cudaEvent_t ev_fork = nullptr, ev_p64 = nullptr, ev_p32 = nullptr;
    if (s1 == nullptr) {
        cudaStreamCreateWithFlags(&s1, cudaStreamNonBlocking);
        cudaStreamCreateWithFlags(&s2, cudaStreamNonBlocking);
        cudaEventCreateWithFlags(&ev_fork, cudaEventDisableTiming);
        cudaEventCreateWithFlags(&ev_p64, cudaEventDisableTiming);
        cudaEventCreateWithFlags(&ev_p32, cudaEventDisableTiming);
    }

    // fork: the two projections run CONCURRENTLY on s1/s2
    cudaEventRecord(ev_fork, 0);
    cudaStreamWaitEvent(s1, ev_fork, 0);
    cudaStreamWaitEvent(s2, ev_fork, 0);
    dim3 gp((NN + 63) / 64, 2, 4);
    k_proj<64><<<gp, 256, 0, s1>>>(h_prev, Wlh, blh, Wrh, brh, 256);
    cudaEventRecord(ev_p64, s1);
    k_proj<32><<<gp, 256, 0, s2>>>(x_t, Wlx, blx, Wrx, brx, 0);
    cudaEventRecord(ev_p32, s2);

    // default stream: counting sort + edge MLP (sorted slots)
    k_init<<<196, 256>>>();
    k_hist<<<EE / 256, 256>>>(ei);
    k_scan_a<<<98, 512>>>();
    k_scan_c<<<98, 512>>>();
    k_scatter<<<EE / 256, 256>>>(ei);
    k_edge_mlp<<<EE / 256, 256>>>(ea, Wm1, bm1, Wm2, bm2);

    // join, then fused GAT (pass-split grid) + finalize
    cudaStreamWaitEvent(0, ev_p64, 0);
    cudaStreamWaitEvent(0, ev_p32, 0);
    k_gat<<<dim3(NN / NPB, 2), 128>>>(Wex, attx, Weh, atth);
    k_final<<<NN / 8, 256>>>(c_prev, biasx, biash, gamma, beta, (float*)d_out);
}

// round 17
// speedup vs baseline: 1.1719x; 1.1719x over previous
#include <cuda_runtime.h>
#include <math.h>
#include <stdint.h>

#define NN 50000
#define EE 800000
#define NPB 16    // nodes per k_gat block (NN % NPB == 0)
#define CHK 128   // edges per staged chunk
#define EST 18    // smem stride (ull) per edge: 144B, 16B-aligned, conflict-limited

typedef unsigned long long ull;

// ---------------- scratch (device globals) ----------------------------------
__device__ int g_cnt[NN];
__device__ int g_rowptr[NN];
__device__ int g_rowfill[NN];
__device__ int g_aux[128];
__device__ int g_src_sorted[EE];
__device__ int g_eid_sorted[EE];
__device__ __align__(16) float g_L[(size_t)NN * 512];
__device__ __align__(16) float g_R[(size_t)NN * 512];
__device__ __align__(16) float g_NUM[(size_t)NN * 512];
__device__ float g_DEN[(size_t)NN * 16];

// ---------------- helpers ----------------------------------------------------
__device__ __forceinline__ ull pack2(float a, float b) {
    ull r; asm("mov.b64 %0,{%1,%2};" : "=l"(r) : "f"(a), "f"(b)); return r;
}
__device__ __forceinline__ void unpack2(float& a, float& b, ull v) {
    asm("mov.b64 {%0,%1},%2;" : "=f"(a), "=f"(b) : "l"(v));
}
__device__ __forceinline__ ull fma2(ull a, ull b, ull c) {
    ull d; asm("fma.rn.f32x2 %0,%1,%2,%3;" : "=l"(d) : "l"(a), "l"(b), "l"(c)); return d;
}
__device__ __forceinline__ ull add2(ull a, ull b) {
    ull d; asm("add.rn.f32x2 %0,%1,%2;" : "=l"(d) : "l"(a), "l"(b)); return d;
}
__device__ __forceinline__ ull mul2(ull a, ull b) {
    ull d; asm("mul.rn.f32x2 %0,%1,%2;" : "=l"(d) : "l"(a), "l"(b)); return d;
}
// L2 eviction policies (createpolicy + cache_hint)
__device__ __forceinline__ ull policy_evict_last() {
    ull p; asm("createpolicy.fractional.L2::evict_last.b64 %0, 1.0;" : "=l"(p));
    return p;
}
__device__ __forceinline__ ull policy_evict_first() {
    ull p; asm("createpolicy.fractional.L2::evict_first.b64 %0, 1.0;" : "=l"(p));
    return p;
}
// sticky-L2 gather load (keeps g_L resident while other traffic streams)
__device__ __forceinline__ ulonglong2 ldg_el(const ull* p, ull pol) {
    ulonglong2 v;
    asm("ld.global.nc.L2::cache_hint.v2.u64 {%0,%1},[%2],%3;"
        : "=l"(v.x), "=l"(v.y) : "l"(p), "l"(pol));
    return v;
}
// streaming store (don't pollute L2 with write-once NUM)
__device__ __forceinline__ void stg_ef(float* p, ull a, ull b, ull pol) {
    asm volatile("st.global.L2::cache_hint.v2.u64 [%0],{%1,%2},%3;"
                 :: "l"(p), "l"(a), "l"(b), "l"(pol) : "memory");
}

// ---------------- counting sort by dst ---------------------------------------
__global__ void k_init() {
    int i = blockIdx.x * 256 + threadIdx.x;
    if (i < NN) g_cnt[i] = 0;
}
__global__ void k_hist(const int* __restrict__ ei) {
    int e = blockIdx.x * 256 + threadIdx.x;
    atomicAdd(&g_cnt[ei[EE + e]], 1);
}
__global__ void k_scan_a() {
    __shared__ int s[512];
    int t = threadIdx.x;
    int i = blockIdx.x * 512 + t;
    int v = (i < NN) ? g_cnt[i] : 0;
    s[t] = v;
    __syncthreads();
#pragma unroll
    for (int off = 1; off < 512; off <<= 1) {
        int u = (t >= off) ? s[t - off] : 0;
        __syncthreads();
        s[t] += u;
        __syncthreads();
    }
    if (i < NN) g_rowptr[i] = s[t] - v;
    if (t == 511) g_aux[blockIdx.x] = s[511];
}
__global__ void k_scan_c() {
    __shared__ int soff;
    int t = threadIdx.x;
    if (t < 32) {
        int sum = 0;
        for (int i = t; i < (int)blockIdx.x; i += 32) sum += g_aux[i];
#pragma unroll
        for (int off = 16; off; off >>= 1)
            sum += __shfl_xor_sync(0xffffffffu, sum, off);
        if (t == 0) soff = sum;
    }
    __syncthreads();
    int i = blockIdx.x * 512 + t;
    if (i < NN) {
        int v = g_rowptr[i] + soff;
        g_rowptr[i] = v;
        g_rowfill[i] = v;
    }
}
__global__ void k_scatter(const int* __restrict__ ei) {
    int e = blockIdx.x * 256 + threadIdx.x;
    int d = ei[EE + e];
    int pos = atomicAdd(&g_rowfill[d], 1);
    g_src_sorted[pos] = ei[e];
    g_eid_sorted[pos] = e;
}

// ---------------- node projections (z-split over gate chunks, f32x2) --------
template <int IN>
__global__ void k_proj(const float* __restrict__ X,
                       const float* __restrict__ W0, const float* __restrict__ B0,
                       const float* __restrict__ W1, const float* __restrict__ B1,
                       int poff) {
    const float* __restrict__ W = blockIdx.y ? W1 : W0;
    const float* __restrict__ B = blockIdx.y ? B1 : B0;
    float* __restrict__ OUT = blockIdx.y ? g_R : g_L;
    int cc = blockIdx.z;

    __shared__ __align__(16) float xs[64 * (IN + 1)];
    __shared__ __align__(16) float ws[IN * 64];
    int t = threadIdx.x;
    int n0 = blockIdx.x * 64;
    for (int idx = t; idx < 64 * IN; idx += 256) {
        int nl = idx / IN, i = idx % IN;
        int n = n0 + nl;
        xs[nl * (IN + 1) + i] = (n < NN) ? X[(size_t)n * IN + i] : 0.f;
    }
    for (int idx = t; idx < IN * 64; idx += 256)
        ws[idx] = W[cc * IN * 64 + idx];
    __syncthreads();

    int nq = t & 15, cq = t >> 4;
    int c0 = cq * 4;
    ull acc[4][2];
#pragma unroll
    for (int r = 0; r < 4; r++) { acc[r][0] = 0; acc[r][1] = 0; }
#pragma unroll 8
    for (int i = 0; i < IN; i++) {
        const ull* wp = (const ull*)&ws[i * 64 + c0];
        ull b01 = wp[0], b23 = wp[1];
#pragma unroll
        for (int r = 0; r < 4; r++) {
            float av = xs[(nq * 4 + r) * (IN + 1) + i];
            ull av2 = pack2(av, av);
            acc[r][0] = fma2(av2, b01, acc[r][0]);
            acc[r][1] = fma2(av2, b23, acc[r][1]);
        }
    }
    float4 bb = *(const float4*)&B[cc * 64 + c0];
    ull bb01 = pack2(bb.x, bb.y), bb23 = pack2(bb.z, bb.w);
#pragma unroll
    for (int r = 0; r < 4; r++) {
        int n = n0 + nq * 4 + r;
        if (n < NN) {
            ulonglong2 ov;
            ov.x = add2(acc[r][0], bb01);
            ov.y = add2(acc[r][1], bb23);
            *(ulonglong2*)&OUT[(size_t)n * 512 + poff + cc * 64 + c0] = ov;
        }
    }
}

// ---------------- fused GAT pass (edge MLP fused into staging) ---------------
// Block = 128 thr = 4 warps; warp w owns concat channels [w*128,(w+1)*128),
// lane owns 4 (ch0). Block owns NPB consecutive dst nodes -> one contiguous
// edge range. Staging now COMPUTES the edge MLP: thread j gathers raw
// edge_attr[eid] (64B) and writes gelu-MLP output dup-packed into smem.
// xl gather prefetch depth 2 with L2 evict_last; next-node xr prefetch;
// NUM streamed evict_first. MLP flops fill k_gat's idle issue slots.
__global__ __launch_bounds__(128, 4)
void k_gat(const float* __restrict__ ea,
           const float* __restrict__ Wm1, const float* __restrict__ bm1,
           const float* __restrict__ Wm2, const float* __restrict__ bm2,
           const float* __restrict__ Wex, const float* __restrict__ attx,
           const float* __restrict__ Weh, const float* __restrict__ atth) {
    __shared__ __align__(16) ull se[CHK * EST];
    __shared__ int ssrc[CHK];
    __shared__ int srow_s[NPB + 1];
    __shared__ float sW1[256], sW2[256], sb1[16], sb2[16];
    int t = threadIdx.x, w = t >> 5, lane = t & 31;
    int n0 = blockIdx.x * NPB;
    if (t <= NPB) srow_s[t] = (n0 + t >= NN) ? EE : g_rowptr[n0 + t];
    for (int idx = t; idx < 256; idx += 128) {
        sW1[idx] = Wm1[idx];
        sW2[idx] = Wm2[idx];
    }
    if (t < 16) { sb1[t] = bm1[t]; sb2[t] = bm2[t]; }

    const ull POL_L = policy_evict_last();
    const ull POL_F = policy_evict_first();

    int ch0 = w * 128 + lane * 4;
    int p = ch0 >> 8, g = (ch0 >> 6) & 3, c = ch0 & 63;
    const float* __restrict__ We = p ? Weh : Wex;
    const float* __restrict__ att = p ? atth : attx;

    ull sw0[16], sw1[16];
#pragma unroll
    for (int k = 0; k < 16; k++) {
        float4 wv = *(const float4*)&We[(g * 16 + k) * 64 + c];
        sw0[k] = pack2(wv.x, wv.y);
        sw1[k] = pack2(wv.z, wv.w);
    }
    float4 a4 = *(const float4*)&att[g * 64 + c];
    int qi = p * 8 + g * 2 + (c >> 5);
    const ull C02 = pack2(0.2f, 0.2f);
    __syncthreads();

    int gstart = srow_s[0];
    int T = srow_s[NPB] - gstart;
    int nchunks = (T + CHK - 1) / CHK;

    int nl = 0;
    ull num0 = 0, num1 = 0;
    float den = 0.f;
    ull xr0, xr1, xr0n, xr1n;
    {
        const ull* rp = (const ull*)(g_R + (size_t)n0 * 512 + ch0);
        xr0 = rp[0]; xr1 = rp[1];
        const ull* rp2 = (const ull*)(g_R + (size_t)(n0 + 1) * 512 + ch0);
        xr0n = rp2[0]; xr1n = rp2[1];
    }

    for (int ci = 0; ci < nchunks; ci++) {
        int base = ci * CHK;
        int cnt = min(CHK, T - base);
        if (ci) __syncthreads();   // previous chunk fully consumed
        // ---- stage chunk: gather raw edge_attr, run MLP, write dup-packed ----
        if (t < cnt) {
            int ge = gstart + base + t;
            ssrc[t] = g_src_sorted[ge];
            int eid = g_eid_sorted[ge];
            float4 va[4];
            const float4* pa = (const float4*)(ea + (size_t)eid * 16);
            va[0] = pa[0]; va[1] = pa[1]; va[2] = pa[2]; va[3] = pa[3];
            const float* a = (const float*)va;
            float h[16];
#pragma unroll
            for (int j = 0; j < 16; j++) {
                float s = sb1[j];
#pragma unroll
                for (int k = 0; k < 16; k++) s = fmaf(a[k], sW1[k * 16 + j], s);
                h[j] = 0.5f * s * (1.0f + erff(s * 0.70710678118654752f));
            }
            ull* q = &se[t * EST];
#pragma unroll
            for (int j = 0; j < 16; j++) {
                float s = sb2[j];
#pragma unroll
                for (int k = 0; k < 16; k++) s = fmaf(h[k], sW2[k * 16 + j], s);
                q[j] = pack2(s, s);
            }
        }
        __syncthreads();

        int cbeg = gstart + base, cend = cbeg + cnt;
        // xl prefetch pipeline, depth 2 (sticky L2)
        ull xlA0, xlA1, xlB0, xlB1;
        {
            int s0 = ssrc[0];
            ulonglong2 v0 = ldg_el((const ull*)(g_L + (size_t)s0 * 512 + ch0), POL_L);
            xlA0 = v0.x; xlA1 = v0.y;
            int s1i = ssrc[cnt > 1 ? 1 : 0];
            ulonglong2 v1 = ldg_el((const ull*)(g_L + (size_t)s1i * 512 + ch0), POL_L);
            xlB0 = v1.x; xlB1 = v1.y;
        }
        while (nl < NPB) {
            int nbeg = srow_s[nl] > cbeg ? srow_s[nl] : cbeg;
            int nend = srow_s[nl + 1] < cend ? srow_s[nl + 1] : cend;
#pragma unroll 4
            for (int ge = nbeg; ge < nend; ge++) {
                int j = ge - cbeg;
                ull xl0 = xlA0, xl1 = xlA1;
                xlA0 = xlB0; xlA1 = xlB1;
                {
                    int jn = (j + 2 < cnt) ? j + 2 : cnt - 1;
                    int sn = ssrc[jn];
                    ulonglong2 v = ldg_el((const ull*)(g_L + (size_t)sn * 512 + ch0), POL_L);
                    xlB0 = v.x;
                    xlB1 = v.y;
                }
                const ulonglong2* ep = (const ulonglong2*)&se[j * EST];
                ull a0 = 0, a1 = 0, b0 = 0, b1 = 0;
#pragma unroll
                for (int k2 = 0; k2 < 8; k2++) {
                    ulonglong2 ek = ep[k2];
                    a0 = fma2(ek.x, sw0[k2 * 2], a0);
                    a1 = fma2(ek.x, sw1[k2 * 2], a1);
                    b0 = fma2(ek.y, sw0[k2 * 2 + 1], b0);
                    b1 = fma2(ek.y, sw1[k2 * 2 + 1], b1);
                }
                ull xs0 = add2(xl0, xr0), xs1 = add2(xl1, xr1);
                ull acc0 = add2(add2(a0, b0), xs0);
                ull acc1 = add2(add2(a1, b1), xs1);
                ull s0x = mul2(acc0, C02), s1x = mul2(acc1, C02);
                float m0, m1, m2, m3, q0, q1, q2, q3;
                unpack2(m0, m1, acc0);
                unpack2(m2, m3, acc1);
                unpack2(q0, q1, s0x);
                unpack2(q2, q3, s1x);
                float l0 = fmaxf(m0, q0), l1 = fmaxf(m1, q1);
                float l2 = fmaxf(m2, q2), l3 = fmaxf(m3, q3);
                float sc = fmaf(l0, a4.x, fmaf(l1, a4.y, fmaf(l2, a4.z, l3 * a4.w)));
                sc += __shfl_xor_sync(0xffffffffu, sc, 1);
                sc += __shfl_xor_sync(0xffffffffu, sc, 2);
                sc += __shfl_xor_sync(0xffffffffu, sc, 4);
                float ex = __expf(sc);
                den += ex;
                ull exx = pack2(ex, ex);
                num0 = fma2(exx, xl0, num0);
                num1 = fma2(exx, xl1, num1);
            }
            if (srow_s[nl + 1] <= cend) {
                stg_ef(g_NUM + (size_t)(n0 + nl) * 512 + ch0, num0, num1, POL_F);
                if ((lane & 7) == 0) g_DEN[(size_t)(n0 + nl) * 16 + qi] = den;
                nl++;
                num0 = num1 = 0;
                den = 0.f;
                xr0 = xr0n; xr1 = xr1n;
                if (nl + 1 < NPB) {   // n0+nl+1 < NN since NN % NPB == 0
                    const ull* rp2 = (const ull*)(g_R + (size_t)(n0 + nl + 1) * 512 + ch0);
                    xr0n = rp2[0];
                    xr1n = rp2[1];
                }
            } else {
                break;
            }
        }
    }
    // flush any remaining (all-empty trailing nodes)
    while (nl < NPB) {
        stg_ef(g_NUM + (size_t)(n0 + nl) * 512 + ch0, num0, num1, POL_F);
        if ((lane & 7) == 0) g_DEN[(size_t)(n0 + nl) * 16 + qi] = den;
        nl++;
        num0 = num1 = 0;
        den = 0.f;
    }
}

// ---------------- final: normalize, LSTM gates, LayerNorm -------------------
__global__ void k_final(const float* __restrict__ c_prev,
                        const float* __restrict__ biasx, const float* __restrict__ biash,
                        const float* __restrict__ gamma, const float* __restrict__ beta,
                        float* __restrict__ out) {
    int w = threadIdx.x >> 5, lane = threadIdx.x & 31;
    int n = blockIdx.x * 8 + w;
    float res[2], cs[2];
    float sum = 0.f, sq = 0.f;
#pragma unroll
    for (int half = 0; half < 2; half++) {
        int ch = lane + half * 32;
        int hh = ch >> 5;
        float a[4];
#pragma unroll
        for (int g = 0; g < 4; g++) {
            float nx = g_NUM[(size_t)n * 512 + g * 64 + ch];
            float nh = g_NUM[(size_t)n * 512 + 256 + g * 64 + ch];
            float dx = g_DEN[(size_t)n * 16 + g * 2 + hh] + 1e-16f;
            float dh = g_DEN[(size_t)n * 16 + 8 + g * 2 + hh] + 1e-16f;
            a[g] = nx / dx + nh / dh + biasx[g * 64 + ch] + biash[g * 64 + ch];
        }
        float it = 1.f / (1.f + __expf(-a[0]));
        float ft = 1.f / (1.f + __expf(-a[1]));
        float ot = 1.f / (1.f + __expf(-a[2]));
        float gt = tanhf(a[3]);
        float cp = c_prev[(size_t)n * 64 + ch];
        float c = ft * cp + it * gt;
        float hp = ot * tanhf(c);
        cs[half] = c;
        res[half] = hp;
        sum += hp;
        sq = fmaf(hp, hp, sq);
    }
#pragma unroll
    for (int off = 16; off; off >>= 1) {
        sum += __shfl_xor_sync(0xffffffffu, sum, off);
        sq += __shfl_xor_sync(0xffffffffu, sq, off);
    }
    float mu = sum * (1.f / 64.f);
    float var = sq * (1.f / 64.f) - mu * mu;
    float inv = rsqrtf(var + 1e-5f);
#pragma unroll
    for (int half = 0; half < 2; half++) {
        int ch = lane + half * 32;
        float hn = (res[half] - mu) * inv * gamma[ch] + beta[ch];
        out[(size_t)n * 64 + ch] = hn;
        out[(size_t)NN * 64 + (size_t)n * 64 + ch] = cs[half];
    }
}

// ---------------- launch ------------------------------------------------------
extern "C" void kernel_launch(void* const* d_in, const int* in_sizes, int n_in,
                              void* d_out, int out_size) {
    const float* x_t    = (const float*)d_in[0];
    const float* h_prev = (const float*)d_in[1];
    const float* c_prev = (const float*)d_in[2];
    const int*   ei     = (const int*)d_in[3];
    const float* ea     = (const float*)d_in[4];
    const float* Wm1    = (const float*)d_in[5];
    const float* bm1    = (const float*)d_in[6];
    const float* Wm2    = (const float*)d_in[7];
    const float* bm2    = (const float*)d_in[8];
    const float* Wlx    = (const float*)d_in[9];
    const float* blx    = (const float*)d_in[10];
    const float* Wrx    = (const float*)d_in[11];
    const float* brx    = (const float*)d_in[12];
    const float* Wex    = (const float*)d_in[13];
    const float* attx   = (const float*)d_in[14];
    const float* biasx  = (const float*)d_in[15];
    const float* Wlh    = (const float*)d_in[16];
    const float* blh    = (const float*)d_in[17];
    const float* Wrh    = (const float*)d_in[18];
    const float* brh    = (const float*)d_in[19];
    const float* Weh    = (const float*)d_in[20];
    const float* atth   = (const float*)d_in[21];
    const float* biash  = (const float*)d_in[22];
    const float* gamma  = (const float*)d_in[23];
    const float* beta   = (const float*)d_in[24];

    // one-time stream/event setup (no device memory involved)
    static cudaStream_t s1 = nullptr, s2 = nullptr;
    static cudaEvent_t ev_fork = nullptr, ev_p64 = nullptr, ev_p32 = nullptr;
    if (s1 == nullptr) {
        cudaStreamCreateWithFlags(&s1, cudaStreamNonBlocking);
        cudaStreamCreateWithFlags(&s2, cudaStreamNonBlocking);
        cudaEventCreateWithFlags(&ev_fork, cudaEventDisableTiming);
        cudaEventCreateWithFlags(&ev_p64, cudaEventDisableTiming);
        cudaEventCreateWithFlags(&ev_p32, cudaEventDisableTiming);
    }

    // fork: the two projections run CONCURRENTLY on s1/s2
    cudaEventRecord(ev_fork, 0);
    cudaStreamWaitEvent(s1, ev_fork, 0);
    cudaStreamWaitEvent(s2, ev_fork, 0);
    dim3 gp((NN + 63) / 64, 2, 4);
    k_proj<64><<<gp, 256, 0, s1>>>(h_prev, Wlh, blh, Wrh, brh, 256);
    cudaEventRecord(ev_p64, s1);
    k_proj<32><<<gp, 256, 0, s2>>>(x_t, Wlx, blx, Wrx, brx, 0);
    cudaEventRecord(ev_p32, s2);

    // default stream: counting sort only (edge MLP fused into k_gat)
    k_init<<<196, 256>>>();
    k_hist<<<EE / 256, 256>>>(ei);
    k_scan_a<<<98, 512>>>();
    k_scan_c<<<98, 512>>>();
    k_scatter<<<EE / 256, 256>>>(ei);

    // join, then fused GAT + finalize
    cudaStreamWaitEvent(0, ev_p64, 0);
    cudaStreamWaitEvent(0, ev_p32, 0);
    k_gat<<<NN / NPB, 128>>>(ea, Wm1, bm1, Wm2, bm2, Wex, attx, Weh, atth);
    k_final<<<NN / 8, 256>>>(c_prev, biasx, biash, gamma, beta, (float*)d_out);
}